// round 16
// baseline (speedup 1.0000x reference)
#include <cuda_runtime.h>
#include <cuda_bf16.h>
#include <cstdint>

// FlaxHouseholderRoPE: B=2, S=4096, H=32, D=128, R=2, fp32. SINGLE kernel.
// One warp per (b,s,h), processing q AND k.
//  - Micro-builder: blocks 0..7 (wave-1, dispatched first) normalize the 64
//    reflector rows into g_u = v*sqrt(2/(|v|^2+eps)), fence, bump g_ready.
//    Consumers issue streamed loads + trig FIRST, then acquire-spin (exposed
//    only for wave-1, overlapped with in-flight LDGs).
//  - g_u is read with __ldcg (coherent L2 path). Round 15 failed because
//    __ldg (ld.global.nc) is NOT coherent with same-launch cross-SM writes.
//  - Reflections: two 2-value butterflies (no |v|^2 reduction, no rcp).
//  - Trig: baked double-precision freq table + Cody-Waite + MUFU (~2e-7).
//  - Counters reset by the last block -> identical work every graph replay.

#define SS 4096
#define HH 32
#define NVEC (2 * SS * HH)        // 262144 vectors per tensor
#define GRID (NVEC / 8)           // 32768 blocks
#define NBUILD 8

__device__ float4 g_u[HH * 2 * 32];    // normalized reflectors (32 KB)
__device__ int    g_ready;             // zero-initialized
__device__ int    g_done;

// inv_freq = 10000^(-i/64): compile-time double-precision table
constexpr double R64 = 0.8659643233600653;   // 10000^(-1/64)
constexpr double rpow(int i) {
    double v = 1.0;
    for (int j = 0; j < i; ++j) v *= R64;
    return v;
}
#define FQ(l) { (float)rpow(2*(l)), (float)rpow(2*(l)+1) }
__device__ const float2 g_freq[32] = {
    FQ(0),  FQ(1),  FQ(2),  FQ(3),  FQ(4),  FQ(5),  FQ(6),  FQ(7),
    FQ(8),  FQ(9),  FQ(10), FQ(11), FQ(12), FQ(13), FQ(14), FQ(15),
    FQ(16), FQ(17), FQ(18), FQ(19), FQ(20), FQ(21), FQ(22), FQ(23),
    FQ(24), FQ(25), FQ(26), FQ(27), FQ(28), FQ(29), FQ(30), FQ(31)
};

__device__ __forceinline__ float dot4(float4 a, float4 b) {
    return a.x * b.x + a.y * b.y + a.z * b.z + a.w * b.w;
}

__global__ __launch_bounds__(256)
void hh_rope_kernel(const float* __restrict__ q,
                    const float* __restrict__ k,
                    const float* __restrict__ pos,
                    const float* __restrict__ refl,
                    float* __restrict__ out) {
    const int tid  = threadIdx.x;
    const int warp = tid >> 5;
    const int lane = tid & 31;
    const int idx  = blockIdx.x * 8 + warp;          // (b*S+s)*H + h
    const int h    = idx & (HH - 1);
    const int s    = (idx >> 5) & (SS - 1);

    // ---- micro-builder: blocks 0..7 normalize one reflector row per warp ----
    if (blockIdx.x < NBUILD) {
        const int row = blockIdx.x * 8 + warp;       // 0..63 == h*2+r
        const float4 v = reinterpret_cast<const float4*>(refl)[row * 32 + lane];
        float sq = dot4(v, v);
        #pragma unroll
        for (int o = 16; o; o >>= 1) sq += __shfl_xor_sync(0xffffffffu, sq, o);
        const float sc = sqrtf(2.0f / (sq + 1e-6f));
        g_u[row * 32 + lane] = make_float4(v.x * sc, v.y * sc, v.z * sc, v.w * sc);
        __threadfence();
        __syncthreads();
        if (tid == 0) atomicAdd(&g_ready, 1);
    }

    // ---- streamed loads FIRST (independent of builders; in flight in spin) ----
    const size_t off = (size_t)idx * 32 + lane;
    float4 xq = __ldcs(reinterpret_cast<const float4*>(q) + off);
    float4 xk = __ldcs(reinterpret_cast<const float4*>(k) + off);

    // ---- trig for this lane's two pairs (baked freqs, CW + MUFU) ----
    const float2 f  = g_freq[lane];                  // L1 hit
    const float  p  = pos[s];
    const float  a0 = p * f.x;
    const float  a1 = p * f.y;
    const float INV2PI = 0.15915494309189535f;
    const float C1 = 6.28125f;                       // n*C1 exact for n <= 652
    const float C2 = 1.9353071795864769e-3f;         // 2*pi - C1
    const float n0 = rintf(a0 * INV2PI);
    const float n1 = rintf(a1 * INV2PI);
    float r0 = fmaf(-n0, C1, a0);  r0 = fmaf(-n0, C2, r0);
    float r1 = fmaf(-n1, C1, a1);  r1 = fmaf(-n1, C2, r1);
    const float c0 = __cosf(r0), s0 = __sinf(r0);
    const float c1 = __cosf(r1), s1 = __sinf(r1);

    // ---- wait for g_u (exposed only in wave 1; loads/trig already done) ----
    if (tid == 0) {
        int r;
        while (true) {
            asm volatile("ld.acquire.gpu.b32 %0, [%1];"
                         : "=r"(r) : "l"(&g_ready) : "memory");
            if (r >= NBUILD) break;
            __nanosleep(32);
        }
    }
    __syncthreads();

    // ---- two normalized-Householder reflections (coherent L2 loads) ----
    #pragma unroll
    for (int r = 0; r < 2; ++r) {
        const float4 u = __ldcg(&g_u[(h * 2 + r) * 32 + lane]);  // L2 hit
        float dq = dot4(xq, u);
        float dk = dot4(xk, u);
        #pragma unroll
        for (int o = 16; o; o >>= 1) {
            dq += __shfl_xor_sync(0xffffffffu, dq, o);
            dk += __shfl_xor_sync(0xffffffffu, dk, o);
        }
        xq.x -= dq * u.x;  xq.y -= dq * u.y;  xq.z -= dq * u.z;  xq.w -= dq * u.w;
        xk.x -= dk * u.x;  xk.y -= dk * u.y;  xk.z -= dk * u.z;  xk.w -= dk * u.w;
    }

    // ---- RoPE with in-register cos/sin ----
    float4 oq, ok;
    oq.x = xq.x * c0 - xq.y * s0;
    oq.y = xq.x * s0 + xq.y * c0;
    oq.z = xq.z * c1 - xq.w * s1;
    oq.w = xq.z * s1 + xq.w * c1;
    ok.x = xk.x * c0 - xk.y * s0;
    ok.y = xk.x * s0 + xk.y * c0;
    ok.z = xk.z * c1 - xk.w * s1;
    ok.w = xk.z * s1 + xk.w * c1;

    float4* out4 = reinterpret_cast<float4*>(out);
    __stcs(out4 + off, oq);                              // q half
    __stcs(out4 + (size_t)NVEC * 32 + off, ok);          // k half

    // ---- reset counters for the next graph replay (last block) ----
    if (tid == 0) {
        const int d = atomicAdd(&g_done, 1);
        if (d == GRID - 1) {
            g_done  = 0;
            g_ready = 0;
            __threadfence();
        }
    }
}

extern "C" void kernel_launch(void* const* d_in, const int* in_sizes, int n_in,
                              void* d_out, int out_size) {
    const float* q    = (const float*)d_in[0];
    const float* k    = (const float*)d_in[1];
    const float* pos  = (const float*)d_in[2];
    const float* refl = (const float*)d_in[3];
    float* out = (float*)d_out;

    hh_rope_kernel<<<GRID, 256>>>(q, k, pos, refl, out);
}